// round 9
// baseline (speedup 1.0000x reference)
#include <cuda_runtime.h>
#include <cstdint>

typedef unsigned long long ull;

// Problem constants (fixed shapes per reference)
#define NN    100000
#define EE    1600000
#define CINn  64
#define COUTn 128
#define SCAN_B 512

// ---------------- scratch (static device globals; no runtime alloc) ----------------
__device__ float g_h0[(size_t)NN * COUTn];
__device__ float g_h1[(size_t)NN * COUTn];
__device__ float g_r[(size_t)NN * COUTn];
__device__ float g_stats[4 * COUTn];
__device__ float g_bnp[4 * COUTn];
// CSR scratch
__device__ int g_deg[NN];
__device__ int g_lscan[NN];
__device__ int g_part[256];
__device__ int g_rowptr[NN + 1];
__device__ int g_cursor[NN];
__device__ int g_eidx[EE];

// ---------------- packed fp32x2 FMA ----------------
#define FMA2(acc, a, w) \
    asm("fma.rn.f32x2 %0, %1, %2, %0;" : "+l"(acc) : "l"(a), "l"(w))

__device__ __forceinline__ ull dup2(float f) {
    ull r;
    asm("mov.b64 %0, {%1, %1};" : "=l"(r) : "f"(f));
    return r;
}

union F2 { ull u; float2 f; };
union W4 { float4 v; ull u[2]; };

// =============================================================================
// CSR build: histogram -> scan -> fill
// =============================================================================
__global__ void hist_kernel(const int* __restrict__ dst, int* __restrict__ deg, int E) {
    const int e = blockIdx.x * blockDim.x + threadIdx.x;
    if (e < E) atomicAdd(&deg[dst[e]], 1);
}

__global__ void scan1_kernel(const int* __restrict__ deg, int* __restrict__ lscan,
                             int* __restrict__ part, int N) {
    __shared__ int sh[SCAN_B];
    const int i = blockIdx.x * SCAN_B + threadIdx.x;
    const int v = (i < N) ? deg[i] : 0;
    sh[threadIdx.x] = v;
    __syncthreads();
#pragma unroll
    for (int off = 1; off < SCAN_B; off <<= 1) {
        int t = (threadIdx.x >= off) ? sh[threadIdx.x - off] : 0;
        __syncthreads();
        sh[threadIdx.x] += t;
        __syncthreads();
    }
    if (i < N) lscan[i] = sh[threadIdx.x] - v;
    if (threadIdx.x == SCAN_B - 1) part[blockIdx.x] = sh[threadIdx.x];
}

__global__ void scan2_kernel(int* __restrict__ part, int nb) {
    __shared__ int sh[256];
    const int v = (threadIdx.x < nb) ? part[threadIdx.x] : 0;
    sh[threadIdx.x] = v;
    __syncthreads();
#pragma unroll
    for (int off = 1; off < 256; off <<= 1) {
        int t = (threadIdx.x >= off) ? sh[threadIdx.x - off] : 0;
        __syncthreads();
        sh[threadIdx.x] += t;
        __syncthreads();
    }
    if (threadIdx.x < nb) part[threadIdx.x] = sh[threadIdx.x] - v;
}

__global__ void scan3_kernel(const int* __restrict__ lscan, const int* __restrict__ part,
                             int* __restrict__ rowptr, int* __restrict__ cursor,
                             int N, int E) {
    const int i = blockIdx.x * blockDim.x + threadIdx.x;
    if (i < N) {
        const int r = lscan[i] + part[i / SCAN_B];
        rowptr[i] = r;
        cursor[i] = r;
    }
    if (i == 0) rowptr[N] = E;
}

__global__ void fill_kernel(const int* __restrict__ src, const int* __restrict__ dst,
                            int* __restrict__ cursor, int* __restrict__ eidx, int E) {
    const int e = blockIdx.x * blockDim.x + threadIdx.x;
    if (e < E) {
        const int pos = atomicAdd(&cursor[dst[e]], 1);
        eidx[pos] = src[e];
    }
}

// =============================================================================
// Fused gather+GEMM: per CTA (64 rows):
//   1) gather agg tile into smem: aggT[m] = sum_{e in-edges of m} f(A[src])
//      where f = relu(bn(.)) if bnA else identity
//   2) C[rows] = f(A[rows]) @ W1^T + aggT @ W2^T + bias  (+ fused BN stats)
// BM=64, BN=128, BK=16, 256 threads, 2 CTAs/SM.
// =============================================================================
template <int K>
__global__ __launch_bounds__(256, 2) void gemm_fused_kernel(
    const float* __restrict__ A, const float* __restrict__ W1,
    const float* __restrict__ W2,
    const int* __restrict__ rowptr, const int* __restrict__ eidx,
    const float* __restrict__ bias, float* __restrict__ C,
    float* __restrict__ stats, const float* __restrict__ bnA, int Nn) {

    extern __shared__ char dsm[];
    float* sh_sum = (float*)dsm;                          // 128
    float* sh_sq  = sh_sum + 128;                         // 128
    float* sbn    = sh_sq + 128;                          // 256
    ull*   As2    = (ull*)(dsm + 2048);                   // 16*66 ull
    float (*Ws)[128] = (float(*)[128])(dsm + 2048 + 16 * 66 * 8);
    float* aggT   = (float*)(dsm + 2048 + 16 * 66 * 8 + 16 * 128 * 4);
    constexpr int AST = K + 4;                            // padded stride

    const int tid  = threadIdx.x;
    const int row0 = blockIdx.x * 64;
    const int warp = tid >> 5;
    const int lane = tid & 31;
    const int tm   = warp * 8;
    const int tn   = lane * 4;

    if (tid < 128) { sh_sum[tid] = 0.f; sh_sq[tid] = 0.f; }
    if (bnA) sbn[tid] = bnA[tid];
    __syncthreads();

    // ---------------- phase G: gather agg tile into smem ----------------
    constexpr int CPT = K / 8;      // cols per thread (8 col-chunks)
    constexpr int NQ4 = CPT / 4;    // float4s per thread (2 for K=64, 4 for K=128)
    const int q8 = tid & 7;
    const int nh = tid >> 3;        // 0..31
    const int c0 = q8 * CPT;

    float4 scf[NQ4], shf[NQ4];
    if (bnA) {
#pragma unroll
        for (int j = 0; j < NQ4; j++) {
            scf[j] = *(const float4*)&sbn[c0 + 4 * j];
            shf[j] = *(const float4*)&sbn[128 + c0 + 4 * j];
        }
    }
#pragma unroll
    for (int h = 0; h < 2; h++) {
        const int m = h * 32 + nh;
        const int grow = row0 + m;
        float4 ga[NQ4];
#pragma unroll
        for (int j = 0; j < NQ4; j++) ga[j] = make_float4(0.f, 0.f, 0.f, 0.f);
        if (grow < Nn) {
            const int beg = __ldg(rowptr + grow);
            const int end = __ldg(rowptr + grow + 1);
            for (int e = beg; e < end; e++) {
                const int s = __ldg(eidx + e);
                const float4* fp = (const float4*)(A + (size_t)s * K + c0);
#pragma unroll
                for (int j = 0; j < NQ4; j++) {
                    float4 v = fp[j];
                    if (bnA) {
                        v.x = fmaxf(fmaf(v.x, scf[j].x, shf[j].x), 0.f);
                        v.y = fmaxf(fmaf(v.y, scf[j].y, shf[j].y), 0.f);
                        v.z = fmaxf(fmaf(v.z, scf[j].z, shf[j].z), 0.f);
                        v.w = fmaxf(fmaf(v.w, scf[j].w, shf[j].w), 0.f);
                    }
                    ga[j].x += v.x; ga[j].y += v.y; ga[j].z += v.z; ga[j].w += v.w;
                }
            }
        }
#pragma unroll
        for (int j = 0; j < NQ4; j++)
            *(float4*)&aggT[m * AST + c0 + 4 * j] = ga[j];
    }
    __syncthreads();

    // ---------------- phase M: two-pass GEMM ----------------
    ull acc2[8][2];
#pragma unroll
    for (int i = 0; i < 8; i++) { acc2[i][0] = 0ull; acc2[i][1] = 0ull; }

    for (int mat = 0; mat < 2; mat++) {
        const float* Wp = mat ? W2 : W1;
        for (int k0 = 0; k0 < K; k0 += 16) {
            // A tile: 64 rows x 16 k, duplicated (a,a)
            {
                const int m  = tid >> 2;
                const int kq = (tid & 3) * 4;
                float4 v;
                if (mat == 0) {
                    const int r = row0 + m;
                    v = make_float4(0.f, 0.f, 0.f, 0.f);
                    if (r < Nn) v = *(const float4*)(A + (size_t)r * K + k0 + kq);
                    if (bnA) {
                        const int cc = k0 + kq;
                        v.x = fmaxf(fmaf(v.x, sbn[cc + 0], sbn[128 + cc + 0]), 0.f);
                        v.y = fmaxf(fmaf(v.y, sbn[cc + 1], sbn[128 + cc + 1]), 0.f);
                        v.z = fmaxf(fmaf(v.z, sbn[cc + 2], sbn[128 + cc + 2]), 0.f);
                        v.w = fmaxf(fmaf(v.w, sbn[cc + 3], sbn[128 + cc + 3]), 0.f);
                    }
                } else {
                    v = *(const float4*)&aggT[m * AST + k0 + kq];  // smem tile
                }
                As2[(kq + 0) * 66 + m] = dup2(v.x);
                As2[(kq + 1) * 66 + m] = dup2(v.y);
                As2[(kq + 2) * 66 + m] = dup2(v.z);
                As2[(kq + 3) * 66 + m] = dup2(v.w);
            }
            // W tile: 128 n x 16 k -> Ws[k][n]
            {
                const int n  = tid >> 1;
                const int kq = (tid & 1) * 8;
                const float* wrow = Wp + (size_t)n * K + k0 + kq;
                float4 v0 = *(const float4*)(wrow);
                float4 v1 = *(const float4*)(wrow + 4);
                Ws[kq + 0][n] = v0.x; Ws[kq + 1][n] = v0.y;
                Ws[kq + 2][n] = v0.z; Ws[kq + 3][n] = v0.w;
                Ws[kq + 4][n] = v1.x; Ws[kq + 5][n] = v1.y;
                Ws[kq + 6][n] = v1.z; Ws[kq + 7][n] = v1.w;
            }
            __syncthreads();
#pragma unroll
            for (int kk = 0; kk < 16; kk++) {
                const ulonglong2* ap = (const ulonglong2*)&As2[kk * 66 + tm];
                const ulonglong2 a01 = ap[0];
                const ulonglong2 a23 = ap[1];
                const ulonglong2 a45 = ap[2];
                const ulonglong2 a67 = ap[3];
                W4 w;
                w.v = *(const float4*)&Ws[kk][tn];
                FMA2(acc2[0][0], a01.x, w.u[0]); FMA2(acc2[0][1], a01.x, w.u[1]);
                FMA2(acc2[1][0], a01.y, w.u[0]); FMA2(acc2[1][1], a01.y, w.u[1]);
                FMA2(acc2[2][0], a23.x, w.u[0]); FMA2(acc2[2][1], a23.x, w.u[1]);
                FMA2(acc2[3][0], a23.y, w.u[0]); FMA2(acc2[3][1], a23.y, w.u[1]);
                FMA2(acc2[4][0], a45.x, w.u[0]); FMA2(acc2[4][1], a45.x, w.u[1]);
                FMA2(acc2[5][0], a45.y, w.u[0]); FMA2(acc2[5][1], a45.y, w.u[1]);
                FMA2(acc2[6][0], a67.x, w.u[0]); FMA2(acc2[6][1], a67.x, w.u[1]);
                FMA2(acc2[7][0], a67.y, w.u[0]); FMA2(acc2[7][1], a67.y, w.u[1]);
            }
            __syncthreads();
        }
    }

    // ---------------- epilogue: bias, store, fused BN stats ----------------
    const float bb0 = __ldg(bias + tn),     bb1 = __ldg(bias + tn + 1);
    const float bb2 = __ldg(bias + tn + 2), bb3 = __ldg(bias + tn + 3);
    float psum[4] = {0.f, 0.f, 0.f, 0.f};
    float psq[4]  = {0.f, 0.f, 0.f, 0.f};
#pragma unroll
    for (int i = 0; i < 8; i++) {
        const int r = row0 + tm + i;
        if (r < Nn) {
            F2 p0, p1;
            p0.u = acc2[i][0];
            p1.u = acc2[i][1];
            float4 o;
            o.x = p0.f.x + bb0; o.y = p0.f.y + bb1;
            o.z = p1.f.x + bb2; o.w = p1.f.y + bb3;
            *(float4*)(C + (size_t)r * 128 + tn) = o;
            psum[0] += o.x; psum[1] += o.y; psum[2] += o.z; psum[3] += o.w;
            psq[0] += o.x * o.x; psq[1] += o.y * o.y;
            psq[2] += o.z * o.z; psq[3] += o.w * o.w;
        }
    }
#pragma unroll
    for (int j = 0; j < 4; j++) {
        atomicAdd(&sh_sum[tn + j], psum[j]);
        atomicAdd(&sh_sq[tn + j], psq[j]);
    }
    __syncthreads();
    if (tid < 128) {
        atomicAdd(&stats[tid], sh_sum[tid]);
        atomicAdd(&stats[128 + tid], sh_sq[tid]);
    }
}

// =============================================================================
// Plain GEMM for the residual projection: r = x @ Wlin^T + blin (K=64)
// =============================================================================
__global__ __launch_bounds__(256) void gemm_r_kernel(
    const float* __restrict__ A, const float* __restrict__ W1,
    const float* __restrict__ bias, float* __restrict__ C, int Nn, int K) {

    __shared__ alignas(16) ull As2[16 * 66];
    __shared__ alignas(16) float Ws[16][128];

    const int tid  = threadIdx.x;
    const int row0 = blockIdx.x * 64;
    const int warp = tid >> 5;
    const int lane = tid & 31;
    const int tm   = warp * 8;
    const int tn   = lane * 4;

    ull acc2[8][2];
#pragma unroll
    for (int i = 0; i < 8; i++) { acc2[i][0] = 0ull; acc2[i][1] = 0ull; }

    for (int k0 = 0; k0 < K; k0 += 16) {
        {
            const int m  = tid >> 2;
            const int kq = (tid & 3) * 4;
            const int r  = row0 + m;
            float4 v = make_float4(0.f, 0.f, 0.f, 0.f);
            if (r < Nn) v = *(const float4*)(A + (size_t)r * K + k0 + kq);
            As2[(kq + 0) * 66 + m] = dup2(v.x);
            As2[(kq + 1) * 66 + m] = dup2(v.y);
            As2[(kq + 2) * 66 + m] = dup2(v.z);
            As2[(kq + 3) * 66 + m] = dup2(v.w);
        }
        {
            const int n  = tid >> 1;
            const int kq = (tid & 1) * 8;
            const float* wrow = W1 + (size_t)n * K + k0 + kq;
            float4 v0 = *(const float4*)(wrow);
            float4 v1 = *(const float4*)(wrow + 4);
            Ws[kq + 0][n] = v0.x; Ws[kq + 1][n] = v0.y;
            Ws[kq + 2][n] = v0.z; Ws[kq + 3][n] = v0.w;
            Ws[kq + 4][n] = v1.x; Ws[kq + 5][n] = v1.y;
            Ws[kq + 6][n] = v1.z; Ws[kq + 7][n] = v1.w;
        }
        __syncthreads();
#pragma unroll
        for (int kk = 0; kk < 16; kk++) {
            const ulonglong2* ap = (const ulonglong2*)&As2[kk * 66 + tm];
            const ulonglong2 a01 = ap[0];
            const ulonglong2 a23 = ap[1];
            const ulonglong2 a45 = ap[2];
            const ulonglong2 a67 = ap[3];
            W4 w;
            w.v = *(const float4*)&Ws[kk][tn];
            FMA2(acc2[0][0], a01.x, w.u[0]); FMA2(acc2[0][1], a01.x, w.u[1]);
            FMA2(acc2[1][0], a01.y, w.u[0]); FMA2(acc2[1][1], a01.y, w.u[1]);
            FMA2(acc2[2][0], a23.x, w.u[0]); FMA2(acc2[2][1], a23.x, w.u[1]);
            FMA2(acc2[3][0], a23.y, w.u[0]); FMA2(acc2[3][1], a23.y, w.u[1]);
            FMA2(acc2[4][0], a45.x, w.u[0]); FMA2(acc2[4][1], a45.x, w.u[1]);
            FMA2(acc2[5][0], a45.y, w.u[0]); FMA2(acc2[5][1], a45.y, w.u[1]);
            FMA2(acc2[6][0], a67.x, w.u[0]); FMA2(acc2[6][1], a67.x, w.u[1]);
            FMA2(acc2[7][0], a67.y, w.u[0]); FMA2(acc2[7][1], a67.y, w.u[1]);
        }
        __syncthreads();
    }

    const float bb0 = bias[tn], bb1 = bias[tn + 1], bb2 = bias[tn + 2], bb3 = bias[tn + 3];
#pragma unroll
    for (int i = 0; i < 8; i++) {
        const int r = row0 + tm + i;
        if (r < Nn) {
            F2 p0, p1;
            p0.u = acc2[i][0];
            p1.u = acc2[i][1];
            float4 o;
            o.x = p0.f.x + bb0; o.y = p0.f.y + bb1;
            o.z = p1.f.x + bb2; o.w = p1.f.y + bb3;
            *(float4*)(C + (size_t)r * 128 + tn) = o;
        }
    }
}

// ---------------- BN finalize ----------------
__global__ void finalize_kernel(const float* __restrict__ stats,
                                const float* __restrict__ gamma,
                                const float* __restrict__ beta,
                                float* __restrict__ bnp, float invN) {
    const int c = threadIdx.x;  // 128 threads
    const float mu   = stats[c] * invN;
    const float var  = stats[128 + c] * invN - mu * mu;
    const float rstd = rsqrtf(var + 1e-5f);
    const float sc   = rstd * gamma[c];
    bnp[c]       = sc;
    bnp[128 + c] = beta[c] - mu * sc;
}

// ---------------- out = relu(h1*scale + shift + r) ----------------
__global__ void final_kernel(const float4* __restrict__ h1, const float* __restrict__ bnp,
                             const float4* __restrict__ r, float4* __restrict__ out,
                             int total4) {
    const int i = blockIdx.x * blockDim.x + threadIdx.x;
    if (i >= total4) return;
    const int c = (i & 31) * 4;
    const float4 v = h1[i];
    const float4 rv = r[i];
    float4 o;
    o.x = fmaxf(fmaf(v.x, bnp[c + 0], bnp[128 + c + 0]) + rv.x, 0.f);
    o.y = fmaxf(fmaf(v.y, bnp[c + 1], bnp[128 + c + 1]) + rv.y, 0.f);
    o.z = fmaxf(fmaf(v.z, bnp[c + 2], bnp[128 + c + 2]) + rv.z, 0.f);
    o.w = fmaxf(fmaf(v.w, bnp[c + 3], bnp[128 + c + 3]) + rv.w, 0.f);
    out[i] = o;
}

// ---------------- launch ----------------
extern "C" void kernel_launch(void* const* d_in, const int* in_sizes, int n_in,
                              void* d_out, int out_size) {
    const float* x    = (const float*)d_in[0];
    const int*   ei   = (const int*)d_in[1];
    const float* Wr0  = (const float*)d_in[2];
    const float* Wn0  = (const float*)d_in[3];
    const float* b0   = (const float*)d_in[4];
    const float* g0   = (const float*)d_in[5];
    const float* be0  = (const float*)d_in[6];
    const float* Wr1  = (const float*)d_in[7];
    const float* Wn1  = (const float*)d_in[8];
    const float* b1   = (const float*)d_in[9];
    const float* g1   = (const float*)d_in[10];
    const float* be1  = (const float*)d_in[11];
    const float* Wlin = (const float*)d_in[12];
    const float* blin = (const float*)d_in[13];
    float* out = (float*)d_out;

    const int N = in_sizes[0] / CINn;
    const int E = in_sizes[1] / 2;
    const int* src = ei;
    const int* dst = ei + E;

    float *h0, *h1, *r, *stats, *bnp;
    int *deg, *lscan, *part, *rowptr, *cursor, *eidx;
    cudaGetSymbolAddress((void**)&h0,     g_h0);
    cudaGetSymbolAddress((void**)&h1,     g_h1);
    cudaGetSymbolAddress((void**)&r,      g_r);
    cudaGetSymbolAddress((void**)&stats,  g_stats);
    cudaGetSymbolAddress((void**)&bnp,    g_bnp);
    cudaGetSymbolAddress((void**)&deg,    g_deg);
    cudaGetSymbolAddress((void**)&lscan,  g_lscan);
    cudaGetSymbolAddress((void**)&part,   g_part);
    cudaGetSymbolAddress((void**)&rowptr, g_rowptr);
    cudaGetSymbolAddress((void**)&cursor, g_cursor);
    cudaGetSymbolAddress((void**)&eidx,   g_eidx);

    // dynamic smem: 2048 + 8448 + 8192 + 64*(K+4)*4
    const int smem64  = 2048 + 8448 + 8192 + 64 * 68 * 4;    // 36096
    const int smem128 = 2048 + 8448 + 8192 + 64 * 132 * 4;   // 52480
    cudaFuncSetAttribute(gemm_fused_kernel<64>,
                         cudaFuncAttributeMaxDynamicSharedMemorySize, smem64);
    cudaFuncSetAttribute(gemm_fused_kernel<128>,
                         cudaFuncAttributeMaxDynamicSharedMemorySize, smem128);

    // side stream + events (created once)
    static cudaStream_t s2 = nullptr;
    static cudaEvent_t ev0 = nullptr, ev1 = nullptr;
    if (!s2) {
        cudaStreamCreate(&s2);
        cudaEventCreateWithFlags(&ev0, cudaEventDisableTiming);
        cudaEventCreateWithFlags(&ev1, cudaEventDisableTiming);
    }

    cudaMemsetAsync(deg,   0, (size_t)N * sizeof(int));
    cudaMemsetAsync(stats, 0, 4 * COUTn * sizeof(float));

    const int nb = (N + SCAN_B - 1) / SCAN_B;
    const int gemmBlocks = (N + 63) / 64;
    const int T4 = N * 32;

    // ---- fork: r = x @ Wlin^T + blin on side stream ----
    cudaEventRecord(ev0, 0);
    cudaStreamWaitEvent(s2, ev0, 0);
    gemm_r_kernel<<<gemmBlocks, 256, 0, s2>>>(x, Wlin, blin, r, N, CINn);
    cudaEventRecord(ev1, s2);

    // ---- main: CSR build ----
    hist_kernel<<<(E + 255) / 256, 256>>>(dst, deg, E);
    scan1_kernel<<<nb, SCAN_B>>>(deg, lscan, part, N);
    scan2_kernel<<<1, 256>>>(part, nb);
    scan3_kernel<<<(N + 255) / 256, 256>>>(lscan, part, rowptr, cursor, N, E);
    fill_kernel<<<(E + 255) / 256, 256>>>(src, dst, cursor, eidx, E);

    // ---- layer 0: fused gather + (x@Wr0 + agg0@Wn0 + b0), BN stats ----
    gemm_fused_kernel<64><<<gemmBlocks, 256, smem64>>>(
        x, Wr0, Wn0, rowptr, eidx, b0, h0, stats, nullptr, N);
    finalize_kernel<<<1, 128>>>(stats, g0, be0, bnp, 1.0f / (float)N);

    // ---- layer 1: fused gather(relu(bn(h0))) + (y@Wr1 + agg1@Wn1 + b1) ----
    gemm_fused_kernel<128><<<gemmBlocks, 256, smem128>>>(
        h0, Wr1, Wn1, rowptr, eidx, b1, h1, stats + 2 * COUTn, bnp, N);
    finalize_kernel<<<1, 128>>>(stats + 2 * COUTn, g1, be1, bnp + 2 * COUTn, 1.0f / (float)N);

    // ---- join r, then out = relu(bn(h1) + r) ----
    cudaStreamWaitEvent(0, ev1, 0);
    final_kernel<<<(T4 + 255) / 256, 256>>>((const float4*)h1, bnp + 2 * COUTn,
                                            (const float4*)r, (float4*)out, T4);
}

// round 10
// speedup vs baseline: 1.2437x; 1.2437x over previous
#include <cuda_runtime.h>
#include <cstdint>

typedef unsigned long long ull;

// Problem constants (fixed shapes per reference)
#define NN    100000
#define EE    1600000
#define CINn  64
#define COUTn 128
#define SCAN_B 512

// ---------------- scratch (static device globals; no runtime alloc) ----------------
__device__ float g_agg0[(size_t)NN * CINn];
__device__ float g_agg1[(size_t)NN * COUTn];
__device__ float g_h0[(size_t)NN * COUTn];
__device__ float g_h1[(size_t)NN * COUTn];
__device__ float g_r[(size_t)NN * COUTn];
__device__ float g_stats[4 * COUTn];
__device__ float g_bnp[4 * COUTn];
// CSR scratch
__device__ int g_deg[NN];
__device__ int g_lscan[NN];
__device__ int g_part[256];
__device__ int g_rowptr[NN + 1];
__device__ int g_cursor[NN];
__device__ int g_eidx[EE];

// ---------------- packed fp32x2 FMA ----------------
#define FMA2(acc, a, w) \
    asm("fma.rn.f32x2 %0, %1, %2, %0;" : "+l"(acc) : "l"(a), "l"(w))

__device__ __forceinline__ ull dup2(float f) {
    ull r;
    asm("mov.b64 %0, {%1, %1};" : "=l"(r) : "f"(f));
    return r;
}

union F2 { ull u; float2 f; };
union W4 { float4 v; ull u[2]; };

// =============================================================================
// CSR build: histogram -> scan -> fill
// =============================================================================
__global__ void hist_kernel(const int* __restrict__ dst, int* __restrict__ deg, int E) {
    const int e = blockIdx.x * blockDim.x + threadIdx.x;
    if (e < E) atomicAdd(&deg[dst[e]], 1);
}

__global__ void scan1_kernel(const int* __restrict__ deg, int* __restrict__ lscan,
                             int* __restrict__ part, int N) {
    __shared__ int sh[SCAN_B];
    const int i = blockIdx.x * SCAN_B + threadIdx.x;
    const int v = (i < N) ? deg[i] : 0;
    sh[threadIdx.x] = v;
    __syncthreads();
#pragma unroll
    for (int off = 1; off < SCAN_B; off <<= 1) {
        int t = (threadIdx.x >= off) ? sh[threadIdx.x - off] : 0;
        __syncthreads();
        sh[threadIdx.x] += t;
        __syncthreads();
    }
    if (i < N) lscan[i] = sh[threadIdx.x] - v;
    if (threadIdx.x == SCAN_B - 1) part[blockIdx.x] = sh[threadIdx.x];
}

__global__ void scan2_kernel(int* __restrict__ part, int nb) {
    __shared__ int sh[256];
    const int v = (threadIdx.x < nb) ? part[threadIdx.x] : 0;
    sh[threadIdx.x] = v;
    __syncthreads();
#pragma unroll
    for (int off = 1; off < 256; off <<= 1) {
        int t = (threadIdx.x >= off) ? sh[threadIdx.x - off] : 0;
        __syncthreads();
        sh[threadIdx.x] += t;
        __syncthreads();
    }
    if (threadIdx.x < nb) part[threadIdx.x] = sh[threadIdx.x] - v;
}

__global__ void scan3_kernel(const int* __restrict__ lscan, const int* __restrict__ part,
                             int* __restrict__ rowptr, int* __restrict__ cursor,
                             int N, int E) {
    const int i = blockIdx.x * blockDim.x + threadIdx.x;
    if (i < N) {
        const int r = lscan[i] + part[i / SCAN_B];
        rowptr[i] = r;
        cursor[i] = r;
    }
    if (i == 0) rowptr[N] = E;
}

__global__ void fill_kernel(const int* __restrict__ src, const int* __restrict__ dst,
                            int* __restrict__ cursor, int* __restrict__ eidx, int E) {
    const int e = blockIdx.x * blockDim.x + threadIdx.x;
    if (e < E) {
        const int pos = atomicAdd(&cursor[dst[e]], 1);
        eidx[pos] = src[e];
    }
}

// =============================================================================
// Gather (layer 0): agg0[n] = sum x[src], 4-edge unrolled, C4=16
// =============================================================================
__global__ void gather0_kernel(const int* __restrict__ rowptr, const int* __restrict__ eidx,
                               const float4* __restrict__ feat, float4* __restrict__ agg,
                               int N) {
    const int g = threadIdx.x >> 4;
    const int c = threadIdx.x & 15;
    const int node = blockIdx.x * 16 + g;
    if (node >= N) return;
    const int beg = rowptr[node];
    const int end = rowptr[node + 1];
    float4 acc = make_float4(0.f, 0.f, 0.f, 0.f);
    int e = beg;
    for (; e + 3 < end; e += 4) {
        const int s0 = eidx[e], s1 = eidx[e + 1], s2 = eidx[e + 2], s3 = eidx[e + 3];
        const float4 v0 = feat[(size_t)s0 * 16 + c];
        const float4 v1 = feat[(size_t)s1 * 16 + c];
        const float4 v2 = feat[(size_t)s2 * 16 + c];
        const float4 v3 = feat[(size_t)s3 * 16 + c];
        acc.x += v0.x + v1.x + v2.x + v3.x;
        acc.y += v0.y + v1.y + v2.y + v3.y;
        acc.z += v0.z + v1.z + v2.z + v3.z;
        acc.w += v0.w + v1.w + v2.w + v3.w;
    }
    for (; e < end; e++) {
        const int s = eidx[e];
        const float4 v = feat[(size_t)s * 16 + c];
        acc.x += v.x; acc.y += v.y; acc.z += v.z; acc.w += v.w;
    }
    agg[(size_t)node * 16 + c] = acc;
}

// =============================================================================
// Gather (layer 1) with fused bn+relu: agg1[n] = sum relu(bn(h0[src])), C4=32
// =============================================================================
__global__ void gather1_kernel(const int* __restrict__ rowptr, const int* __restrict__ eidx,
                               const float4* __restrict__ h0, const float* __restrict__ bnp,
                               float4* __restrict__ agg, int N) {
    const int g = threadIdx.x >> 5;
    const int c = threadIdx.x & 31;
    const int node = blockIdx.x * 8 + g;
    if (node >= N) return;
    const float sc0 = bnp[c * 4 + 0], sh0 = bnp[128 + c * 4 + 0];
    const float sc1 = bnp[c * 4 + 1], sh1 = bnp[128 + c * 4 + 1];
    const float sc2 = bnp[c * 4 + 2], sh2 = bnp[128 + c * 4 + 2];
    const float sc3 = bnp[c * 4 + 3], sh3 = bnp[128 + c * 4 + 3];
    const int beg = rowptr[node];
    const int end = rowptr[node + 1];
    float4 acc = make_float4(0.f, 0.f, 0.f, 0.f);
    int e = beg;
    for (; e + 3 < end; e += 4) {
        const int s0 = eidx[e], s1 = eidx[e + 1], s2 = eidx[e + 2], s3 = eidx[e + 3];
        const float4 v0 = h0[(size_t)s0 * 32 + c];
        const float4 v1 = h0[(size_t)s1 * 32 + c];
        const float4 v2 = h0[(size_t)s2 * 32 + c];
        const float4 v3 = h0[(size_t)s3 * 32 + c];
        acc.x += fmaxf(fmaf(v0.x, sc0, sh0), 0.f) + fmaxf(fmaf(v1.x, sc0, sh0), 0.f)
               + fmaxf(fmaf(v2.x, sc0, sh0), 0.f) + fmaxf(fmaf(v3.x, sc0, sh0), 0.f);
        acc.y += fmaxf(fmaf(v0.y, sc1, sh1), 0.f) + fmaxf(fmaf(v1.y, sc1, sh1), 0.f)
               + fmaxf(fmaf(v2.y, sc1, sh1), 0.f) + fmaxf(fmaf(v3.y, sc1, sh1), 0.f);
        acc.z += fmaxf(fmaf(v0.z, sc2, sh2), 0.f) + fmaxf(fmaf(v1.z, sc2, sh2), 0.f)
               + fmaxf(fmaf(v2.z, sc2, sh2), 0.f) + fmaxf(fmaf(v3.z, sc2, sh2), 0.f);
        acc.w += fmaxf(fmaf(v0.w, sc3, sh3), 0.f) + fmaxf(fmaf(v1.w, sc3, sh3), 0.f)
               + fmaxf(fmaf(v2.w, sc3, sh3), 0.f) + fmaxf(fmaf(v3.w, sc3, sh3), 0.f);
    }
    for (; e < end; e++) {
        const int s = eidx[e];
        const float4 v = h0[(size_t)s * 32 + c];
        acc.x += fmaxf(fmaf(v.x, sc0, sh0), 0.f);
        acc.y += fmaxf(fmaf(v.y, sc1, sh1), 0.f);
        acc.z += fmaxf(fmaf(v.z, sc2, sh2), 0.f);
        acc.w += fmaxf(fmaf(v.w, sc3, sh3), 0.f);
    }
    agg[(size_t)node * 32 + c] = acc;
}

// =============================================================================
// Tiled fp32x2 GEMM: C = A@W1^T (+ B@W2^T) [+ C if accumC] + bias(if set).
// BM=64, BN=128, BK=16, 256 threads. Optional fused BN stats; optional bnA
// (apply relu(bn(A)) while staging A, mat 0 only).
// =============================================================================
__global__ __launch_bounds__(256) void gemm_kernel(
    const float* __restrict__ A, const float* __restrict__ W1,
    const float* __restrict__ B, const float* __restrict__ W2,
    const float* __restrict__ bias, float* __restrict__ C,
    float* __restrict__ stats, const float* __restrict__ bnA,
    int Nn, int K, int accumC) {

    __shared__ alignas(16) ull As2[16 * 66];   // [k][m] dup pairs, stride 66
    __shared__ alignas(16) float Ws[16][128];
    __shared__ float sh_sum[128];
    __shared__ float sh_sq[128];
    __shared__ float sbn[256];

    const int tid  = threadIdx.x;
    const int row0 = blockIdx.x * 64;
    const int warp = tid >> 5;
    const int lane = tid & 31;
    const int tm   = warp * 8;   // 8 rows per thread
    const int tn   = lane * 4;   // 4 cols per thread

    if (stats && tid < 128) { sh_sum[tid] = 0.f; sh_sq[tid] = 0.f; }
    if (bnA) sbn[tid] = bnA[tid];   // scale[0:128] | shift[0:128] (K==128 case)
    __syncthreads();

    ull acc2[8][2];
#pragma unroll
    for (int i = 0; i < 8; i++) { acc2[i][0] = 0ull; acc2[i][1] = 0ull; }

    const int nmat = (B != nullptr) ? 2 : 1;
    for (int mat = 0; mat < nmat; mat++) {
        const float* Ap = mat ? B : A;
        const float* Wp = mat ? W2 : W1;
        for (int k0 = 0; k0 < K; k0 += 16) {
            // A tile: 64 rows x 16 k, stored duplicated (a,a)
            {
                const int m  = tid >> 2;
                const int kq = (tid & 3) * 4;
                const int r  = row0 + m;
                float4 v = make_float4(0.f, 0.f, 0.f, 0.f);
                if (r < Nn) v = *(const float4*)(Ap + (size_t)r * K + k0 + kq);
                if (bnA && mat == 0) {
                    const int cc = k0 + kq;
                    v.x = fmaxf(fmaf(v.x, sbn[cc + 0], sbn[128 + cc + 0]), 0.f);
                    v.y = fmaxf(fmaf(v.y, sbn[cc + 1], sbn[128 + cc + 1]), 0.f);
                    v.z = fmaxf(fmaf(v.z, sbn[cc + 2], sbn[128 + cc + 2]), 0.f);
                    v.w = fmaxf(fmaf(v.w, sbn[cc + 3], sbn[128 + cc + 3]), 0.f);
                }
                As2[(kq + 0) * 66 + m] = dup2(v.x);
                As2[(kq + 1) * 66 + m] = dup2(v.y);
                As2[(kq + 2) * 66 + m] = dup2(v.z);
                As2[(kq + 3) * 66 + m] = dup2(v.w);
            }
            // W tile: 128 n x 16 k -> Ws[k][n]
            {
                const int n  = tid >> 1;
                const int kq = (tid & 1) * 8;
                const float* wrow = Wp + (size_t)n * K + k0 + kq;
                float4 v0 = *(const float4*)(wrow);
                float4 v1 = *(const float4*)(wrow + 4);
                Ws[kq + 0][n] = v0.x; Ws[kq + 1][n] = v0.y;
                Ws[kq + 2][n] = v0.z; Ws[kq + 3][n] = v0.w;
                Ws[kq + 4][n] = v1.x; Ws[kq + 5][n] = v1.y;
                Ws[kq + 6][n] = v1.z; Ws[kq + 7][n] = v1.w;
            }
            __syncthreads();
#pragma unroll
            for (int kk = 0; kk < 16; kk++) {
                const ulonglong2* ap = (const ulonglong2*)&As2[kk * 66 + tm];
                const ulonglong2 a01 = ap[0];   // LDS.128 broadcast
                const ulonglong2 a23 = ap[1];
                const ulonglong2 a45 = ap[2];
                const ulonglong2 a67 = ap[3];
                W4 w;
                w.v = *(const float4*)&Ws[kk][tn];   // LDS.128
                FMA2(acc2[0][0], a01.x, w.u[0]); FMA2(acc2[0][1], a01.x, w.u[1]);
                FMA2(acc2[1][0], a01.y, w.u[0]); FMA2(acc2[1][1], a01.y, w.u[1]);
                FMA2(acc2[2][0], a23.x, w.u[0]); FMA2(acc2[2][1], a23.x, w.u[1]);
                FMA2(acc2[3][0], a23.y, w.u[0]); FMA2(acc2[3][1], a23.y, w.u[1]);
                FMA2(acc2[4][0], a45.x, w.u[0]); FMA2(acc2[4][1], a45.x, w.u[1]);
                FMA2(acc2[5][0], a45.y, w.u[0]); FMA2(acc2[5][1], a45.y, w.u[1]);
                FMA2(acc2[6][0], a67.x, w.u[0]); FMA2(acc2[6][1], a67.x, w.u[1]);
                FMA2(acc2[7][0], a67.y, w.u[0]); FMA2(acc2[7][1], a67.y, w.u[1]);
            }
            __syncthreads();
        }
    }

    // ---------------- epilogue: (accum), bias, store, fused BN stats ----------------
    const float bb0 = bias ? bias[tn]     : 0.f;
    const float bb1 = bias ? bias[tn + 1] : 0.f;
    const float bb2 = bias ? bias[tn + 2] : 0.f;
    const float bb3 = bias ? bias[tn + 3] : 0.f;
    float psum[4] = {0.f, 0.f, 0.f, 0.f};
    float psq[4]  = {0.f, 0.f, 0.f, 0.f};
#pragma unroll
    for (int i = 0; i < 8; i++) {
        const int r = row0 + tm + i;
        if (r < Nn) {
            F2 p0, p1;
            p0.u = acc2[i][0];
            p1.u = acc2[i][1];
            float4 o;
            o.x = p0.f.x + bb0; o.y = p0.f.y + bb1;
            o.z = p1.f.x + bb2; o.w = p1.f.y + bb3;
            if (accumC) {
                const float4 prev = *(const float4*)(C + (size_t)r * 128 + tn);
                o.x += prev.x; o.y += prev.y; o.z += prev.z; o.w += prev.w;
            }
            *(float4*)(C + (size_t)r * 128 + tn) = o;
            psum[0] += o.x; psum[1] += o.y; psum[2] += o.z; psum[3] += o.w;
            psq[0] += o.x * o.x; psq[1] += o.y * o.y;
            psq[2] += o.z * o.z; psq[3] += o.w * o.w;
        }
    }
    if (stats) {
#pragma unroll
        for (int j = 0; j < 4; j++) {
            atomicAdd(&sh_sum[tn + j], psum[j]);
            atomicAdd(&sh_sq[tn + j], psq[j]);
        }
        __syncthreads();
        if (tid < 128) {
            atomicAdd(&stats[tid], sh_sum[tid]);
            atomicAdd(&stats[128 + tid], sh_sq[tid]);
        }
    }
}

// ---------------- BN finalize ----------------
__global__ void finalize_kernel(const float* __restrict__ stats,
                                const float* __restrict__ gamma,
                                const float* __restrict__ beta,
                                float* __restrict__ bnp, float invN) {
    const int c = threadIdx.x;  // 128 threads
    const float mu   = stats[c] * invN;
    const float var  = stats[128 + c] * invN - mu * mu;
    const float rstd = rsqrtf(var + 1e-5f);
    const float sc   = rstd * gamma[c];
    bnp[c]       = sc;
    bnp[128 + c] = beta[c] - mu * sc;
}

// ---------------- out = relu(h1*scale + shift + r) ----------------
__global__ void final_kernel(const float4* __restrict__ h1, const float* __restrict__ bnp,
                             const float4* __restrict__ r, float4* __restrict__ out,
                             int total4) {
    const int i = blockIdx.x * blockDim.x + threadIdx.x;
    if (i >= total4) return;
    const int c = (i & 31) * 4;
    const float4 v = h1[i];
    const float4 rv = r[i];
    float4 o;
    o.x = fmaxf(fmaf(v.x, bnp[c + 0], bnp[128 + c + 0]) + rv.x, 0.f);
    o.y = fmaxf(fmaf(v.y, bnp[c + 1], bnp[128 + c + 1]) + rv.y, 0.f);
    o.z = fmaxf(fmaf(v.z, bnp[c + 2], bnp[128 + c + 2]) + rv.z, 0.f);
    o.w = fmaxf(fmaf(v.w, bnp[c + 3], bnp[128 + c + 3]) + rv.w, 0.f);
    out[i] = o;
}

// ---------------- launch ----------------
extern "C" void kernel_launch(void* const* d_in, const int* in_sizes, int n_in,
                              void* d_out, int out_size) {
    const float* x    = (const float*)d_in[0];
    const int*   ei   = (const int*)d_in[1];
    const float* Wr0  = (const float*)d_in[2];
    const float* Wn0  = (const float*)d_in[3];
    const float* b0   = (const float*)d_in[4];
    const float* g0   = (const float*)d_in[5];
    const float* be0  = (const float*)d_in[6];
    const float* Wr1  = (const float*)d_in[7];
    const float* Wn1  = (const float*)d_in[8];
    const float* b1   = (const float*)d_in[9];
    const float* g1   = (const float*)d_in[10];
    const float* be1  = (const float*)d_in[11];
    const float* Wlin = (const float*)d_in[12];
    const float* blin = (const float*)d_in[13];
    float* out = (float*)d_out;

    const int N = in_sizes[0] / CINn;
    const int E = in_sizes[1] / 2;
    const int* src = ei;
    const int* dst = ei + E;

    float *agg0, *agg1, *h0, *h1, *r, *stats, *bnp;
    int *deg, *lscan, *part, *rowptr, *cursor, *eidx;
    cudaGetSymbolAddress((void**)&agg0,   g_agg0);
    cudaGetSymbolAddress((void**)&agg1,   g_agg1);
    cudaGetSymbolAddress((void**)&h0,     g_h0);
    cudaGetSymbolAddress((void**)&h1,     g_h1);
    cudaGetSymbolAddress((void**)&r,      g_r);
    cudaGetSymbolAddress((void**)&stats,  g_stats);
    cudaGetSymbolAddress((void**)&bnp,    g_bnp);
    cudaGetSymbolAddress((void**)&deg,    g_deg);
    cudaGetSymbolAddress((void**)&lscan,  g_lscan);
    cudaGetSymbolAddress((void**)&part,   g_part);
    cudaGetSymbolAddress((void**)&rowptr, g_rowptr);
    cudaGetSymbolAddress((void**)&cursor, g_cursor);
    cudaGetSymbolAddress((void**)&eidx,   g_eidx);

    // side streams + fork/join events (created once; capture turns event
    // record/wait into graph edges)
    static cudaStream_t s2 = nullptr, s3 = nullptr;
    static cudaEvent_t ev0 = nullptr, ev1 = nullptr, ev2 = nullptr, ev3 = nullptr;
    static cudaEvent_t evF = nullptr, evG = nullptr;
    if (!s2) {
        cudaStreamCreate(&s2);
        cudaStreamCreate(&s3);
        cudaEventCreateWithFlags(&ev0, cudaEventDisableTiming);
        cudaEventCreateWithFlags(&ev1, cudaEventDisableTiming);
        cudaEventCreateWithFlags(&ev2, cudaEventDisableTiming);
        cudaEventCreateWithFlags(&ev3, cudaEventDisableTiming);
        cudaEventCreateWithFlags(&evF, cudaEventDisableTiming);
        cudaEventCreateWithFlags(&evG, cudaEventDisableTiming);
    }

    cudaMemsetAsync(deg,   0, (size_t)N * sizeof(int));
    cudaMemsetAsync(stats, 0, 4 * COUTn * sizeof(float));

    const int nb = (N + SCAN_B - 1) / SCAN_B;
    const int gemmBlocks = (N + 63) / 64;
    const int T4 = N * 32;

    // ---- fork: r = x @ Wlin^T + blin on s2 (independent) ----
    cudaEventRecord(ev0, 0);
    cudaStreamWaitEvent(s2, ev0, 0);
    gemm_kernel<<<gemmBlocks, 256, 0, s2>>>(x, Wlin, nullptr, nullptr, blin, r,
                                            nullptr, nullptr, N, CINn, 0);
    cudaEventRecord(ev1, s2);

    // ---- main: CSR build ----
    hist_kernel<<<(E + 255) / 256, 256>>>(dst, deg, E);
    scan1_kernel<<<nb, SCAN_B>>>(deg, lscan, part, N);
    scan2_kernel<<<1, 256>>>(part, nb);
    scan3_kernel<<<(N + 255) / 256, 256>>>(lscan, part, rowptr, cursor, N, E);
    fill_kernel<<<(E + 255) / 256, 256>>>(src, dst, cursor, eidx, E);
    cudaEventRecord(evF, 0);

    // ---- fork: gather0 on s3 (needs CSR) ∥ main gemm0a (needs only x) ----
    cudaStreamWaitEvent(s3, evF, 0);
    gather0_kernel<<<(N + 15) / 16, 256, 0, s3>>>(rowptr, eidx, (const float4*)x,
                                                  (float4*)agg0, N);
    cudaEventRecord(evG, s3);

    // main (concurrent with gather0): h0 = x @ Wr0^T + b0
    gemm_kernel<<<gemmBlocks, 256>>>(x, Wr0, nullptr, nullptr, b0, h0,
                                     nullptr, nullptr, N, CINn, 0);

    // join gather0, then h0 += agg0 @ Wn0^T (+ fused BN stats on final h0)
    cudaStreamWaitEvent(0, evG, 0);
    gemm_kernel<<<gemmBlocks, 256>>>(agg0, Wn0, nullptr, nullptr, nullptr, h0,
                                     stats, nullptr, N, CINn, 1);
    finalize_kernel<<<1, 128>>>(stats, g0, be0, bnp, 1.0f / (float)N);

    // ---- fork: gather1 (needs h0, bnp) on s2 ----
    cudaEventRecord(ev2, 0);
    cudaStreamWaitEvent(s2, ev2, 0);
    gather1_kernel<<<(N + 7) / 8, 256, 0, s2>>>(rowptr, eidx, (const float4*)h0, bnp,
                                                (float4*)agg1, N);
    cudaEventRecord(ev3, s2);

    // ---- main (concurrent with gather1): h1 = relu(bn(h0)) @ Wr1^T + b1 ----
    gemm_kernel<<<gemmBlocks, 256>>>(h0, Wr1, nullptr, nullptr, b1, h1,
                                     nullptr, bnp, N, COUTn, 0);

    // ---- join, then h1 += agg1 @ Wn1^T (+ fused BN stats over final h1) ----
    cudaStreamWaitEvent(0, ev3, 0);
    gemm_kernel<<<gemmBlocks, 256>>>(agg1, Wn1, nullptr, nullptr, nullptr, h1,
                                     stats + 2 * COUTn, nullptr, N, COUTn, 1);
    finalize_kernel<<<1, 128>>>(stats + 2 * COUTn, g1, be1, bnp + 2 * COUTn, 1.0f / (float)N);

    // ---- join r, then out = relu(bn(h1) + r) ----
    cudaStreamWaitEvent(0, ev1, 0);
    final_kernel<<<(T4 + 255) / 256, 256>>>((const float4*)h1, bnp + 2 * COUTn,
                                            (const float4*)r, (float4*)out, T4);
}

// round 11
// speedup vs baseline: 1.2701x; 1.0212x over previous
#include <cuda_runtime.h>
#include <cstdint>

typedef unsigned long long ull;

// Problem constants (fixed shapes per reference)
#define NN    100000
#define EE    1600000
#define CINn  64
#define COUTn 128
#define SCAN_B 512

// ---------------- scratch (static device globals; no runtime alloc) ----------------
__device__ float g_agg0[(size_t)NN * CINn];
__device__ float g_agg1[(size_t)NN * COUTn];
__device__ float g_h0[(size_t)NN * COUTn];
__device__ float g_h1[(size_t)NN * COUTn];
__device__ float g_r[(size_t)NN * COUTn];
__device__ float g_stats[4 * COUTn];
__device__ float g_bnp[4 * COUTn];
// CSR scratch
__device__ int g_deg[NN];
__device__ int g_lscan[NN];
__device__ int g_part[256];
__device__ int g_rowptr[NN + 1];
__device__ int g_cursor[NN];
__device__ int g_eidx[EE];

// ---------------- packed fp32x2 FMA ----------------
#define FMA2(acc, a, w) \
    asm("fma.rn.f32x2 %0, %1, %2, %0;" : "+l"(acc) : "l"(a), "l"(w))

__device__ __forceinline__ ull dup2(float f) {
    ull r;
    asm("mov.b64 %0, {%1, %1};" : "=l"(r) : "f"(f));
    return r;
}

union F2 { ull u; float2 f; };
union W4 { float4 v; ull u[2]; };

// =============================================================================
// CSR build: histogram -> scan -> fill
// =============================================================================
__global__ void hist_kernel(const int* __restrict__ dst, int* __restrict__ deg, int E) {
    const int e = blockIdx.x * blockDim.x + threadIdx.x;
    if (e < E) atomicAdd(&deg[dst[e]], 1);
}

__global__ void scan1_kernel(const int* __restrict__ deg, int* __restrict__ lscan,
                             int* __restrict__ part, int N) {
    __shared__ int sh[SCAN_B];
    const int i = blockIdx.x * SCAN_B + threadIdx.x;
    const int v = (i < N) ? deg[i] : 0;
    sh[threadIdx.x] = v;
    __syncthreads();
#pragma unroll
    for (int off = 1; off < SCAN_B; off <<= 1) {
        int t = (threadIdx.x >= off) ? sh[threadIdx.x - off] : 0;
        __syncthreads();
        sh[threadIdx.x] += t;
        __syncthreads();
    }
    if (i < N) lscan[i] = sh[threadIdx.x] - v;
    if (threadIdx.x == SCAN_B - 1) part[blockIdx.x] = sh[threadIdx.x];
}

__global__ void scan2_kernel(int* __restrict__ part, int nb) {
    __shared__ int sh[256];
    const int v = (threadIdx.x < nb) ? part[threadIdx.x] : 0;
    sh[threadIdx.x] = v;
    __syncthreads();
#pragma unroll
    for (int off = 1; off < 256; off <<= 1) {
        int t = (threadIdx.x >= off) ? sh[threadIdx.x - off] : 0;
        __syncthreads();
        sh[threadIdx.x] += t;
        __syncthreads();
    }
    if (threadIdx.x < nb) part[threadIdx.x] = sh[threadIdx.x] - v;
}

__global__ void scan3_kernel(const int* __restrict__ lscan, const int* __restrict__ part,
                             int* __restrict__ rowptr, int* __restrict__ cursor,
                             int N, int E) {
    const int i = blockIdx.x * blockDim.x + threadIdx.x;
    if (i < N) {
        const int r = lscan[i] + part[i / SCAN_B];
        rowptr[i] = r;
        cursor[i] = r;
    }
    if (i == 0) rowptr[N] = E;
}

__global__ void fill_kernel(const int* __restrict__ src, const int* __restrict__ dst,
                            int* __restrict__ cursor, int* __restrict__ eidx, int E) {
    const int e = blockIdx.x * blockDim.x + threadIdx.x;
    if (e < E) {
        const int pos = atomicAdd(&cursor[dst[e]], 1);
        eidx[pos] = src[e];
    }
}

// =============================================================================
// Gather (layer 0): agg0[n] = sum x[src], 4-edge unrolled, C4=16
// =============================================================================
__global__ void gather0_kernel(const int* __restrict__ rowptr, const int* __restrict__ eidx,
                               const float4* __restrict__ feat, float4* __restrict__ agg,
                               int N) {
    const int g = threadIdx.x >> 4;
    const int c = threadIdx.x & 15;
    const int node = blockIdx.x * 16 + g;
    if (node >= N) return;
    const int beg = rowptr[node];
    const int end = rowptr[node + 1];
    float4 acc = make_float4(0.f, 0.f, 0.f, 0.f);
    int e = beg;
    for (; e + 3 < end; e += 4) {
        const int s0 = eidx[e], s1 = eidx[e + 1], s2 = eidx[e + 2], s3 = eidx[e + 3];
        const float4 v0 = feat[(size_t)s0 * 16 + c];
        const float4 v1 = feat[(size_t)s1 * 16 + c];
        const float4 v2 = feat[(size_t)s2 * 16 + c];
        const float4 v3 = feat[(size_t)s3 * 16 + c];
        acc.x += v0.x + v1.x + v2.x + v3.x;
        acc.y += v0.y + v1.y + v2.y + v3.y;
        acc.z += v0.z + v1.z + v2.z + v3.z;
        acc.w += v0.w + v1.w + v2.w + v3.w;
    }
    for (; e < end; e++) {
        const int s = eidx[e];
        const float4 v = feat[(size_t)s * 16 + c];
        acc.x += v.x; acc.y += v.y; acc.z += v.z; acc.w += v.w;
    }
    agg[(size_t)node * 16 + c] = acc;
}

// =============================================================================
// Gather (layer 1) with fused bn+relu: agg1[n] = sum relu(bn(h0[src])), C4=32
// =============================================================================
__global__ void gather1_kernel(const int* __restrict__ rowptr, const int* __restrict__ eidx,
                               const float4* __restrict__ h0, const float* __restrict__ bnp,
                               float4* __restrict__ agg, int N) {
    const int g = threadIdx.x >> 5;
    const int c = threadIdx.x & 31;
    const int node = blockIdx.x * 8 + g;
    if (node >= N) return;
    const float sc0 = bnp[c * 4 + 0], sh0 = bnp[128 + c * 4 + 0];
    const float sc1 = bnp[c * 4 + 1], sh1 = bnp[128 + c * 4 + 1];
    const float sc2 = bnp[c * 4 + 2], sh2 = bnp[128 + c * 4 + 2];
    const float sc3 = bnp[c * 4 + 3], sh3 = bnp[128 + c * 4 + 3];
    const int beg = rowptr[node];
    const int end = rowptr[node + 1];
    float4 acc = make_float4(0.f, 0.f, 0.f, 0.f);
    int e = beg;
    for (; e + 3 < end; e += 4) {
        const int s0 = eidx[e], s1 = eidx[e + 1], s2 = eidx[e + 2], s3 = eidx[e + 3];
        const float4 v0 = h0[(size_t)s0 * 32 + c];
        const float4 v1 = h0[(size_t)s1 * 32 + c];
        const float4 v2 = h0[(size_t)s2 * 32 + c];
        const float4 v3 = h0[(size_t)s3 * 32 + c];
        acc.x += fmaxf(fmaf(v0.x, sc0, sh0), 0.f) + fmaxf(fmaf(v1.x, sc0, sh0), 0.f)
               + fmaxf(fmaf(v2.x, sc0, sh0), 0.f) + fmaxf(fmaf(v3.x, sc0, sh0), 0.f);
        acc.y += fmaxf(fmaf(v0.y, sc1, sh1), 0.f) + fmaxf(fmaf(v1.y, sc1, sh1), 0.f)
               + fmaxf(fmaf(v2.y, sc1, sh1), 0.f) + fmaxf(fmaf(v3.y, sc1, sh1), 0.f);
        acc.z += fmaxf(fmaf(v0.z, sc2, sh2), 0.f) + fmaxf(fmaf(v1.z, sc2, sh2), 0.f)
               + fmaxf(fmaf(v2.z, sc2, sh2), 0.f) + fmaxf(fmaf(v3.z, sc2, sh2), 0.f);
        acc.w += fmaxf(fmaf(v0.w, sc3, sh3), 0.f) + fmaxf(fmaf(v1.w, sc3, sh3), 0.f)
               + fmaxf(fmaf(v2.w, sc3, sh3), 0.f) + fmaxf(fmaf(v3.w, sc3, sh3), 0.f);
    }
    for (; e < end; e++) {
        const int s = eidx[e];
        const float4 v = h0[(size_t)s * 32 + c];
        acc.x += fmaxf(fmaf(v.x, sc0, sh0), 0.f);
        acc.y += fmaxf(fmaf(v.y, sc1, sh1), 0.f);
        acc.z += fmaxf(fmaf(v.z, sc2, sh2), 0.f);
        acc.w += fmaxf(fmaf(v.w, sc3, sh3), 0.f);
    }
    agg[(size_t)node * 32 + c] = acc;
}

// =============================================================================
// Double-buffered fp32x2 GEMM: C = A@W1^T (+ B@W2^T) [+ C if accumC] + bias.
// BM=64, BN=128, BK=16, 256 threads. Software pipeline: LDG for step s+1 is
// issued before computing step s; STS into the other smem buffer; ONE sync
// per step. Optional fused BN stats; optional bnA (relu(bn(A)) on mat 0).
// =============================================================================
__global__ __launch_bounds__(256) void gemm_kernel(
    const float* __restrict__ A, const float* __restrict__ W1,
    const float* __restrict__ B, const float* __restrict__ W2,
    const float* __restrict__ bias, float* __restrict__ C,
    float* __restrict__ stats, const float* __restrict__ bnA,
    int Nn, int K, int accumC) {

    __shared__ alignas(16) ull As2[2][16 * 66];   // 2 x 8448 B
    __shared__ alignas(16) float Ws[2][16][128];  // 2 x 8192 B
    __shared__ float sh_sum[128];
    __shared__ float sh_sq[128];
    __shared__ float sbn[256];

    const int tid  = threadIdx.x;
    const int row0 = blockIdx.x * 64;
    const int warp = tid >> 5;
    const int lane = tid & 31;
    const int tm   = warp * 8;   // 8 rows per thread
    const int tn   = lane * 4;   // 4 cols per thread

    if (stats && tid < 128) { sh_sum[tid] = 0.f; sh_sq[tid] = 0.f; }
    if (bnA) sbn[tid] = bnA[tid];
    __syncthreads();

    const int ksPerMat = K >> 4;
    const int totSteps = (B != nullptr) ? 2 * ksPerMat : ksPerMat;

    // per-thread staging coordinates (fixed)
    const int am  = tid >> 2;            // A row within tile
    const int akq = (tid & 3) * 4;       // A k-quad
    const int wn  = tid >> 1;            // W n within tile
    const int wkq = (tid & 1) * 8;       // W k-oct

    // load step s into registers
    auto LOAD = [&](int s, float4& va, float4& vw0, float4& vw1) {
        const int mt = (s >= ksPerMat) ? 1 : 0;
        const int k0 = (s - mt * ksPerMat) << 4;
        const float* Ap = mt ? B : A;
        const float* Wp = mt ? W2 : W1;
        const int rr = row0 + am;
        va = make_float4(0.f, 0.f, 0.f, 0.f);
        if (rr < Nn) va = *(const float4*)(Ap + (size_t)rr * K + k0 + akq);
        if (bnA && mt == 0) {
            const int cc = k0 + akq;
            va.x = fmaxf(fmaf(va.x, sbn[cc + 0], sbn[128 + cc + 0]), 0.f);
            va.y = fmaxf(fmaf(va.y, sbn[cc + 1], sbn[128 + cc + 1]), 0.f);
            va.z = fmaxf(fmaf(va.z, sbn[cc + 2], sbn[128 + cc + 2]), 0.f);
            va.w = fmaxf(fmaf(va.w, sbn[cc + 3], sbn[128 + cc + 3]), 0.f);
        }
        const float* wrow = Wp + (size_t)wn * K + k0 + wkq;
        vw0 = *(const float4*)(wrow);
        vw1 = *(const float4*)(wrow + 4);
    };
    // store registers into smem buffer b
    auto STORE = [&](int b, const float4& va, const float4& vw0, const float4& vw1) {
        As2[b][(akq + 0) * 66 + am] = dup2(va.x);
        As2[b][(akq + 1) * 66 + am] = dup2(va.y);
        As2[b][(akq + 2) * 66 + am] = dup2(va.z);
        As2[b][(akq + 3) * 66 + am] = dup2(va.w);
        Ws[b][wkq + 0][wn] = vw0.x; Ws[b][wkq + 1][wn] = vw0.y;
        Ws[b][wkq + 2][wn] = vw0.z; Ws[b][wkq + 3][wn] = vw0.w;
        Ws[b][wkq + 4][wn] = vw1.x; Ws[b][wkq + 5][wn] = vw1.y;
        Ws[b][wkq + 6][wn] = vw1.z; Ws[b][wkq + 7][wn] = vw1.w;
    };

    ull acc2[8][2];
#pragma unroll
    for (int i = 0; i < 8; i++) { acc2[i][0] = 0ull; acc2[i][1] = 0ull; }

    // prologue
    {
        float4 va, vw0, vw1;
        LOAD(0, va, vw0, vw1);
        STORE(0, va, vw0, vw1);
    }
    __syncthreads();

    for (int s = 0; s < totSteps; s++) {
        const int cur = s & 1;
        float4 va, vw0, vw1;
        const bool more = (s + 1 < totSteps);
        if (more) LOAD(s + 1, va, vw0, vw1);   // LDG in flight during compute
#pragma unroll
        for (int kk = 0; kk < 16; kk++) {
            const ulonglong2* ap = (const ulonglong2*)&As2[cur][kk * 66 + tm];
            const ulonglong2 a01 = ap[0];
            const ulonglong2 a23 = ap[1];
            const ulonglong2 a45 = ap[2];
            const ulonglong2 a67 = ap[3];
            W4 w;
            w.v = *(const float4*)&Ws[cur][kk][tn];
            FMA2(acc2[0][0], a01.x, w.u[0]); FMA2(acc2[0][1], a01.x, w.u[1]);
            FMA2(acc2[1][0], a01.y, w.u[0]); FMA2(acc2[1][1], a01.y, w.u[1]);
            FMA2(acc2[2][0], a23.x, w.u[0]); FMA2(acc2[2][1], a23.x, w.u[1]);
            FMA2(acc2[3][0], a23.y, w.u[0]); FMA2(acc2[3][1], a23.y, w.u[1]);
            FMA2(acc2[4][0], a45.x, w.u[0]); FMA2(acc2[4][1], a45.x, w.u[1]);
            FMA2(acc2[5][0], a45.y, w.u[0]); FMA2(acc2[5][1], a45.y, w.u[1]);
            FMA2(acc2[6][0], a67.x, w.u[0]); FMA2(acc2[6][1], a67.x, w.u[1]);
            FMA2(acc2[7][0], a67.y, w.u[0]); FMA2(acc2[7][1], a67.y, w.u[1]);
        }
        if (more) STORE(cur ^ 1, va, vw0, vw1);
        __syncthreads();
    }

    // ---------------- epilogue: (accum), bias, store, fused BN stats ----------------
    const float bb0 = bias ? bias[tn]     : 0.f;
    const float bb1 = bias ? bias[tn + 1] : 0.f;
    const float bb2 = bias ? bias[tn + 2] : 0.f;
    const float bb3 = bias ? bias[tn + 3] : 0.f;
    float psum[4] = {0.f, 0.f, 0.f, 0.f};
    float psq[4]  = {0.f, 0.f, 0.f, 0.f};
#pragma unroll
    for (int i = 0; i < 8; i++) {
        const int r = row0 + tm + i;
        if (r < Nn) {
            F2 p0, p1;
            p0.u = acc2[i][0];
            p1.u = acc2[i][1];
            float4 o;
            o.x = p0.f.x + bb0; o.y = p0.f.y + bb1;
            o.z = p1.f.x + bb2; o.w = p1.f.y + bb3;
            if (accumC) {
                const float4 prev = *(const float4*)(C + (size_t)r * 128 + tn);
                o.x += prev.x; o.y += prev.y; o.z += prev.z; o.w += prev.w;
            }
            *(float4*)(C + (size_t)r * 128 + tn) = o;
            psum[0] += o.x; psum[1] += o.y; psum[2] += o.z; psum[3] += o.w;
            psq[0] += o.x * o.x; psq[1] += o.y * o.y;
            psq[2] += o.z * o.z; psq[3] += o.w * o.w;
        }
    }
    if (stats) {
#pragma unroll
        for (int j = 0; j < 4; j++) {
            atomicAdd(&sh_sum[tn + j], psum[j]);
            atomicAdd(&sh_sq[tn + j], psq[j]);
        }
        __syncthreads();
        if (tid < 128) {
            atomicAdd(&stats[tid], sh_sum[tid]);
            atomicAdd(&stats[128 + tid], sh_sq[tid]);
        }
    }
}

// ---------------- BN finalize ----------------
__global__ void finalize_kernel(const float* __restrict__ stats,
                                const float* __restrict__ gamma,
                                const float* __restrict__ beta,
                                float* __restrict__ bnp, float invN) {
    const int c = threadIdx.x;  // 128 threads
    const float mu   = stats[c] * invN;
    const float var  = stats[128 + c] * invN - mu * mu;
    const float rstd = rsqrtf(var + 1e-5f);
    const float sc   = rstd * gamma[c];
    bnp[c]       = sc;
    bnp[128 + c] = beta[c] - mu * sc;
}

// ---------------- out = relu(h1*scale + shift + r) ----------------
__global__ void final_kernel(const float4* __restrict__ h1, const float* __restrict__ bnp,
                             const float4* __restrict__ r, float4* __restrict__ out,
                             int total4) {
    const int i = blockIdx.x * blockDim.x + threadIdx.x;
    if (i >= total4) return;
    const int c = (i & 31) * 4;
    const float4 v = h1[i];
    const float4 rv = r[i];
    float4 o;
    o.x = fmaxf(fmaf(v.x, bnp[c + 0], bnp[128 + c + 0]) + rv.x, 0.f);
    o.y = fmaxf(fmaf(v.y, bnp[c + 1], bnp[128 + c + 1]) + rv.y, 0.f);
    o.z = fmaxf(fmaf(v.z, bnp[c + 2], bnp[128 + c + 2]) + rv.z, 0.f);
    o.w = fmaxf(fmaf(v.w, bnp[c + 3], bnp[128 + c + 3]) + rv.w, 0.f);
    out[i] = o;
}

// ---------------- launch (exact round-8 structure) ----------------
extern "C" void kernel_launch(void* const* d_in, const int* in_sizes, int n_in,
                              void* d_out, int out_size) {
    const float* x    = (const float*)d_in[0];
    const int*   ei   = (const int*)d_in[1];
    const float* Wr0  = (const float*)d_in[2];
    const float* Wn0  = (const float*)d_in[3];
    const float* b0   = (const float*)d_in[4];
    const float* g0   = (const float*)d_in[5];
    const float* be0  = (const float*)d_in[6];
    const float* Wr1  = (const float*)d_in[7];
    const float* Wn1  = (const float*)d_in[8];
    const float* b1   = (const float*)d_in[9];
    const float* g1   = (const float*)d_in[10];
    const float* be1  = (const float*)d_in[11];
    const float* Wlin = (const float*)d_in[12];
    const float* blin = (const float*)d_in[13];
    float* out = (float*)d_out;

    const int N = in_sizes[0] / CINn;
    const int E = in_sizes[1] / 2;
    const int* src = ei;
    const int* dst = ei + E;

    float *agg0, *agg1, *h0, *h1, *r, *stats, *bnp;
    int *deg, *lscan, *part, *rowptr, *cursor, *eidx;
    cudaGetSymbolAddress((void**)&agg0,   g_agg0);
    cudaGetSymbolAddress((void**)&agg1,   g_agg1);
    cudaGetSymbolAddress((void**)&h0,     g_h0);
    cudaGetSymbolAddress((void**)&h1,     g_h1);
    cudaGetSymbolAddress((void**)&r,      g_r);
    cudaGetSymbolAddress((void**)&stats,  g_stats);
    cudaGetSymbolAddress((void**)&bnp,    g_bnp);
    cudaGetSymbolAddress((void**)&deg,    g_deg);
    cudaGetSymbolAddress((void**)&lscan,  g_lscan);
    cudaGetSymbolAddress((void**)&part,   g_part);
    cudaGetSymbolAddress((void**)&rowptr, g_rowptr);
    cudaGetSymbolAddress((void**)&cursor, g_cursor);
    cudaGetSymbolAddress((void**)&eidx,   g_eidx);

    // side stream + fork/join events (created once)
    static cudaStream_t s2 = nullptr;
    static cudaEvent_t ev0 = nullptr, ev1 = nullptr, ev2 = nullptr, ev3 = nullptr;
    if (!s2) {
        cudaStreamCreate(&s2);
        cudaEventCreateWithFlags(&ev0, cudaEventDisableTiming);
        cudaEventCreateWithFlags(&ev1, cudaEventDisableTiming);
        cudaEventCreateWithFlags(&ev2, cudaEventDisableTiming);
        cudaEventCreateWithFlags(&ev3, cudaEventDisableTiming);
    }

    cudaMemsetAsync(deg,   0, (size_t)N * sizeof(int));
    cudaMemsetAsync(stats, 0, 4 * COUTn * sizeof(float));

    const int nb = (N + SCAN_B - 1) / SCAN_B;
    const int gemmBlocks = (N + 63) / 64;
    const int T4 = N * 32;

    // ---- fork: r = x @ Wlin^T + blin on side stream ----
    cudaEventRecord(ev0, 0);
    cudaStreamWaitEvent(s2, ev0, 0);
    gemm_kernel<<<gemmBlocks, 256, 0, s2>>>(x, Wlin, nullptr, nullptr, blin, r,
                                            nullptr, nullptr, N, CINn, 0);
    cudaEventRecord(ev1, s2);

    // ---- main: CSR build + layer-0 aggregation ----
    hist_kernel<<<(E + 255) / 256, 256>>>(dst, deg, E);
    scan1_kernel<<<nb, SCAN_B>>>(deg, lscan, part, N);
    scan2_kernel<<<1, 256>>>(part, nb);
    scan3_kernel<<<(N + 255) / 256, 256>>>(lscan, part, rowptr, cursor, N, E);
    fill_kernel<<<(E + 255) / 256, 256>>>(src, dst, cursor, eidx, E);
    gather0_kernel<<<(N + 15) / 16, 256>>>(rowptr, eidx, (const float4*)x,
                                           (float4*)agg0, N);

    // h0 = x @ Wr0^T + agg0 @ Wn0^T + b0 (+ fused BN stats)
    gemm_kernel<<<gemmBlocks, 256>>>(x, Wr0, agg0, Wn0, b0, h0,
                                     stats, nullptr, N, CINn, 0);
    finalize_kernel<<<1, 128>>>(stats, g0, be0, bnp, 1.0f / (float)N);

    // ---- fork: gather1 (needs h0, bnp) on side stream ----
    cudaEventRecord(ev2, 0);
    cudaStreamWaitEvent(s2, ev2, 0);
    gather1_kernel<<<(N + 7) / 8, 256, 0, s2>>>(rowptr, eidx, (const float4*)h0, bnp,
                                                (float4*)agg1, N);
    cudaEventRecord(ev3, s2);

    // ---- main (concurrent with gather1): h1 = relu(bn(h0)) @ Wr1^T + b1 ----
    gemm_kernel<<<gemmBlocks, 256>>>(h0, Wr1, nullptr, nullptr, b1, h1,
                                     nullptr, bnp, N, COUTn, 0);

    // ---- join, then h1 += agg1 @ Wn1^T (+ fused BN stats over final h1) ----
    cudaStreamWaitEvent(0, ev3, 0);
    gemm_kernel<<<gemmBlocks, 256>>>(agg1, Wn1, nullptr, nullptr, nullptr, h1,
                                     stats + 2 * COUTn, nullptr, N, COUTn, 1);
    finalize_kernel<<<1, 128>>>(stats + 2 * COUTn, g1, be1, bnp + 2 * COUTn, 1.0f / (float)N);

    // ---- join r, then out = relu(bn(h1) + r) ----
    cudaStreamWaitEvent(0, ev1, 0);
    final_kernel<<<(T4 + 255) / 256, 256>>>((const float4*)h1, bnp + 2 * COUTn,
                                            (const float4*)r, (float4*)out, T4);
}